// round 3
// baseline (speedup 1.0000x reference)
#include <cuda_runtime.h>

#define Bc   2
#define Mq   16384
#define Np   4096
#define Cin  128
#define CsF  256
#define DoC  128
#define NCOLS (Bc*Mq)
#define NBLK  256
#define PH   2048
#define LDW  136      // k-major smem tile pad (floats): bank = 8*tg+g, conflict-free
#define LDXP 72       // gemmP X tile pad (64-wide)
#define LDZ  136
#define LDZP 72

// ---------------- scratch (device globals) ----------------
__device__ __align__(16) float d_W1hi[384*128];
__device__ __align__(16) float d_W1lo[384*128];
__device__ __align__(16) float d_W2hi[128*128];
__device__ __align__(16) float d_W2lo[128*128];
__device__ __align__(16) float d_P  [Bc*Np*DoC];
__device__ float d_cd[Bc*Mq*6];
__device__ int   d_ci[Bc*Mq*6];
__device__ int   d_idx[Bc*Mq*3];
__device__ float d_w  [Bc*Mq*3];
__device__ __align__(16) float d_z1 [Bc*DoC*Mq];
__device__ __align__(16) float d_z2 [Bc*DoC*Mq];
__device__ float d_psum[NBLK*DoC];
__device__ float d_psq [NBLK*DoC];
__device__ float d_bn1[2*DoC];
__device__ float d_bn2[2*DoC];

// ---------------- helpers ----------------
__device__ __forceinline__ void cp16(float* s, const float* g) {
  unsigned sa = (unsigned)__cvta_generic_to_shared(s);
  asm volatile("cp.async.cg.shared.global [%0], [%1], 16;\n" :: "r"(sa), "l"(g));
}
__device__ __forceinline__ void cp_commit() { asm volatile("cp.async.commit_group;\n"); }
template<int N> __device__ __forceinline__ void cp_wait() {
  asm volatile("cp.async.wait_group %0;\n" :: "n"(N));
}
__device__ __forceinline__ void mma8(float* d, const unsigned* a, const unsigned* b) {
  asm("mma.sync.aligned.m16n8k8.row.col.f32.tf32.tf32.f32 "
      "{%0,%1,%2,%3}, {%4,%5,%6,%7}, {%8,%9}, {%0,%1,%2,%3};"
      : "+f"(d[0]), "+f"(d[1]), "+f"(d[2]), "+f"(d[3])
      : "r"(a[0]), "r"(a[1]), "r"(a[2]), "r"(a[3]), "r"(b[0]), "r"(b[1]));
}

// 3xTF32 inner compute over one 32-k chunk.
// W tiles: k-major [32][LDW] (hi/lo, tf32-masked floats). X tile: [32][LX] raw fp32.
// Warp computes [ob..ob+32) x [mb..mb+8*NT) of the block tile.
template<int NT, int LX>
__device__ __forceinline__ void chunk_mma(const float* Wh, const float* Wl, const float* Xp,
                                          int g, int tg, int ob, int mb,
                                          float (&acc)[2][NT][4]) {
  #pragma unroll
  for (int s = 0; s < 4; s++) {
    int kr = s * 8;
    unsigned ah[2][4], al[2][4];
    #pragma unroll
    for (int i = 0; i < 2; i++) {
      int o0 = ob + 16*i + g;
      const float* w0 = Wh + (kr+tg)*LDW;
      const float* w1 = Wh + (kr+tg+4)*LDW;
      ah[i][0] = __float_as_uint(w0[o0]);
      ah[i][1] = __float_as_uint(w0[o0+8]);
      ah[i][2] = __float_as_uint(w1[o0]);
      ah[i][3] = __float_as_uint(w1[o0+8]);
      const float* v0 = Wl + (kr+tg)*LDW;
      const float* v1 = Wl + (kr+tg+4)*LDW;
      al[i][0] = __float_as_uint(v0[o0]);
      al[i][1] = __float_as_uint(v0[o0+8]);
      al[i][2] = __float_as_uint(v1[o0]);
      al[i][3] = __float_as_uint(v1[o0+8]);
    }
    #pragma unroll
    for (int n = 0; n < NT; n++) {
      float x0 = Xp[(kr+tg)*LX + mb + 8*n + g];
      float x1 = Xp[(kr+tg+4)*LX + mb + 8*n + g];
      unsigned bh[2], bl[2];
      bh[0] = __float_as_uint(x0) & 0xffffe000u;
      bh[1] = __float_as_uint(x1) & 0xffffe000u;
      float r0 = x0 - __uint_as_float(bh[0]);
      float r1 = x1 - __uint_as_float(bh[1]);
      bl[0] = __float_as_uint(r0) & 0xffffe000u;
      bl[1] = __float_as_uint(r1) & 0xffffe000u;
      mma8(acc[0][n], al[0], bh);
      mma8(acc[0][n], ah[0], bl);
      mma8(acc[0][n], ah[0], bh);
      mma8(acc[1][n], al[1], bh);
      mma8(acc[1][n], ah[1], bl);
      mma8(acc[1][n], ah[1], bh);
    }
  }
}

// ---------------- W transpose + tf32 hi/lo split ----------------
__global__ __launch_bounds__(256) void split_w_kernel(
    const float* __restrict__ W1, const float* __restrict__ W2) {
  int e = blockIdx.x * 256 + threadIdx.x;   // 65536 total
  float w; float* hi; float* lo; int idx;
  if (e < 384*128) {
    int k = e >> 7, o = e & 127;
    w = W1[o*384 + k]; hi = d_W1hi; lo = d_W1lo; idx = e;
  } else {
    int e2 = e - 384*128;
    int k = e2 >> 7, o = e2 & 127;
    w = W2[o*128 + k]; hi = d_W2hi; lo = d_W2lo; idx = e2;
  }
  float h = __uint_as_float(__float_as_uint(w) & 0xffffe000u);
  float l = w - h;
  l = __uint_as_float(__float_as_uint(l) & 0xffffe000u);
  hi[idx] = h; lo[idx] = l;
}

// ---------------- 3-NN search: 2 queries/thread, split point dim in 2 ----------------
__global__ __launch_bounds__(256) void knn_kernel(
    const float* __restrict__ xyz, const float* __restrict__ sub_xyz) {
  __shared__ float4 pts[PH];   // 32KB
  int bx = blockIdx.x;                      // 128 blocks
  int b    = bx >> 6;
  int half = (bx >> 5) & 1;
  int m0   = ((bx & 31) << 9) + threadIdx.x;   // queries m0 and m0+256
  const float* sp = sub_xyz + (size_t)b * 3 * Np + half * PH;
  for (int i = threadIdx.x; i < PH; i += 256) {
    float px = sp[i], py = sp[Np + i], pz = sp[2*Np + i];
    pts[i] = make_float4(px, py, pz, fmaf(px, px, fmaf(py, py, pz*pz)));
  }
  __syncthreads();
  const float* qp = xyz + (size_t)b * 3 * Mq;
  int mA = m0, mB = m0 + 256;
  float nxA = -2.f*qp[mA], nyA = -2.f*qp[Mq+mA], nzA = -2.f*qp[2*Mq+mA];
  float nxB = -2.f*qp[mB], nyB = -2.f*qp[Mq+mB], nzB = -2.f*qp[2*Mq+mB];

  float a0=3.4e38f,a1=3.4e38f,a2=3.4e38f; int ja0=0,ja1=0,ja2=0;
  float b0=3.4e38f,b1=3.4e38f,b2=3.4e38f; int jb0=0,jb1=0,jb2=0;
  #pragma unroll 4
  for (int i = 0; i < PH; i++) {
    float4 p = pts[i];
    float eA = fmaf(nxA, p.x, fmaf(nyA, p.y, fmaf(nzA, p.z, p.w)));
    float eB = fmaf(nxB, p.x, fmaf(nyB, p.y, fmaf(nzB, p.z, p.w)));
    if (eA < a2) {
      if (eA < a1) {
        a2 = a1; ja2 = ja1;
        if (eA < a0) { a1 = a0; ja1 = ja0; a0 = eA; ja0 = i; }
        else         { a1 = eA; ja1 = i; }
      } else { a2 = eA; ja2 = i; }
    }
    if (eB < b2) {
      if (eB < b1) {
        b2 = b1; jb2 = jb1;
        if (eB < b0) { b1 = b0; jb1 = jb0; b0 = eB; jb0 = i; }
        else         { b1 = eB; jb1 = i; }
      } else { b2 = eB; jb2 = i; }
    }
  }
  int off = half * PH;
  size_t baseA = ((size_t)(b * Mq + mA) * 2 + half) * 3;
  d_cd[baseA+0]=a0; d_cd[baseA+1]=a1; d_cd[baseA+2]=a2;
  d_ci[baseA+0]=ja0+off; d_ci[baseA+1]=ja1+off; d_ci[baseA+2]=ja2+off;
  size_t baseB = ((size_t)(b * Mq + mB) * 2 + half) * 3;
  d_cd[baseB+0]=b0; d_cd[baseB+1]=b1; d_cd[baseB+2]=b2;
  d_ci[baseB+0]=jb0+off; d_ci[baseB+1]=jb1+off; d_ci[baseB+2]=jb2+off;
}

// ---------------- merge 6 candidates -> final idx/weights ----------------
__global__ __launch_bounds__(256) void knn_merge_kernel(const float* __restrict__ xyz) {
  int g = blockIdx.x * 256 + threadIdx.x;   // 0..32767
  int b = g >> 14, m = g & (Mq - 1);
  const float* qp = xyz + (size_t)b * 3 * Mq;
  float qx = qp[m], qy = qp[Mq + m], qz = qp[2*Mq + m];
  float qq = fmaf(qx, qx, fmaf(qy, qy, qz*qz));
  float c0 = 3.4e38f, c1 = 3.4e38f, c2 = 3.4e38f;
  int j0 = 0, j1 = 0, j2 = 0;
  size_t base = (size_t)g * 6;
  #pragma unroll
  for (int t = 0; t < 6; t++) {
    float e = d_cd[base + t];
    int  id = d_ci[base + t];
    if (e < c2) {
      if (e < c1) {
        c2 = c1; j2 = j1;
        if (e < c0) { c1 = c0; j1 = j0; c0 = e; j0 = id; }
        else        { c1 = e; j1 = id; }
      } else { c2 = e; j2 = id; }
    }
  }
  float d0  = fmaxf(c0 + qq, 0.0f);
  float d1  = fmaxf(c1 + qq, 0.0f);
  float d2v = fmaxf(c2 + qq, 0.0f);
  float w0 = 1.0f / (d0 + 1e-8f);
  float w1 = 1.0f / (d1 + 1e-8f);
  float w2 = 1.0f / (d2v + 1e-8f);
  float inv = 1.0f / (w0 + w1 + w2);
  d_idx[g*3+0]=j0; d_idx[g*3+1]=j1; d_idx[g*3+2]=j2;
  d_w[g*3+0]=w0*inv; d_w[g*3+1]=w1*inv; d_w[g*3+2]=w2*inv;
}

// ---------------- P = W1[:,128:384] @ sub_x, stored [b][n][o], 3xTF32 mma ----------------
__global__ __launch_bounds__(256) void gemmP_kernel(const float* __restrict__ sub_x) {
  extern __shared__ float smem[];
  float* Whi = smem;             // [2][32*136] = 8704
  float* Wlo = smem + 8704;      // 8704
  float* Xs  = smem + 17408;     // [2][32*72]  = 4608
  float* Zs  = smem;             // epilogue reuse: 128*72 = 9216
  int tid = threadIdx.x;
  int lane = tid & 31, warp = tid >> 5;
  int g = lane >> 2, tg = lane & 3;
  int ob = (warp & 3) * 32, mb = (warp >> 2) * 32;
  int bx = blockIdx.x;
  int b = bx >> 6, n0 = (bx & 63) << 6;
  const float* xb = sub_x + (size_t)b * CsF * Np;

  float acc[2][4][4];
  #pragma unroll
  for (int i = 0; i < 2; i++)
    #pragma unroll
    for (int n = 0; n < 4; n++)
      #pragma unroll
      for (int r = 0; r < 4; r++) acc[i][n][r] = 0.0f;

  auto load_chunk = [&](int kc, int s) {
    float* Wh = Whi + s*4352; float* Wl = Wlo + s*4352; float* Xd = Xs + s*2304;
    #pragma unroll
    for (int k = 0; k < 4; k++) {
      int e4 = tid + k*256, kk = e4 >> 5, c = (e4 & 31) << 2;
      cp16(Wh + kk*LDW + c, d_W1hi + (size_t)(Cin + kc + kk)*128 + c);
      cp16(Wl + kk*LDW + c, d_W1lo + (size_t)(Cin + kc + kk)*128 + c);
    }
    #pragma unroll
    for (int k = 0; k < 2; k++) {
      int e4 = tid + k*256, kk = e4 >> 4, c = (e4 & 15) << 2;
      cp16(Xd + kk*LDXP + c, xb + (size_t)(kc + kk)*Np + n0 + c);
    }
  };
  load_chunk(0, 0); cp_commit();
  for (int ch = 0; ch < 8; ch++) {
    if (ch < 7) { load_chunk((ch+1)*32, (ch+1)&1); cp_commit(); cp_wait<1>(); }
    else        { cp_wait<0>(); }
    __syncthreads();
    chunk_mma<4, LDXP>(Whi + (ch&1)*4352, Wlo + (ch&1)*4352, Xs + (ch&1)*2304,
                       g, tg, ob, mb, acc);
    __syncthreads();
  }

  // acc -> Zs[o][n] (pad 72), then coalesced-ish store to P[n][o]
  #pragma unroll
  for (int i = 0; i < 2; i++)
    #pragma unroll
    for (int n = 0; n < 4; n++) {
      int o = ob + 16*i + g;
      int m = mb + 8*n + 2*tg;
      *(float2*)&Zs[(size_t)o*LDZP + m]     = make_float2(acc[i][n][0], acc[i][n][1]);
      *(float2*)&Zs[(size_t)(o+8)*LDZP + m] = make_float2(acc[i][n][2], acc[i][n][3]);
    }
  __syncthreads();
  int nl = tid & 63, oh = tid >> 6;   // 4 o-quarters
  float* dst = d_P + ((size_t)b * Np + n0 + nl) * 128;
  #pragma unroll
  for (int o = oh*32; o < oh*32 + 32; o += 4) {
    float4 v = make_float4(Zs[(o+0)*LDZP + nl], Zs[(o+1)*LDZP + nl],
                           Zs[(o+2)*LDZP + nl], Zs[(o+3)*LDZP + nl]);
    *(float4*)(dst + o) = v;
  }
}

// ---------------- z1 = W1a @ x + gather(P), + block stats (3xTF32 mma) ----------------
__global__ __launch_bounds__(256) void gemm1_kernel(const float* __restrict__ x) {
  extern __shared__ float smem[];
  float* Whi = smem;                   // [2][4352]
  float* Wlo = smem + 8704;
  float* Xs  = smem + 17408;           // [2][4352]
  float* Zs  = smem;                   // epilogue reuse: 128*136 = 17408
  int*   sidx = (int*)(smem + 26112);  // 384
  float* sw   = smem + 26112 + 384;    // 384
  int tid = threadIdx.x;
  int lane = tid & 31, warp = tid >> 5;
  int g = lane >> 2, tg = lane & 3;
  int ob = (warp & 3) * 32, mb = (warp >> 2) * 64;
  int bx = blockIdx.x;
  int b = bx >> 7, m0 = (bx & 127) << 7;
  const float* xb = x + (size_t)b * Cin * Mq;

  {
    size_t cb = ((size_t)(b * Mq + m0)) * 3;
    for (int e = tid; e < 384; e += 256) { sidx[e] = d_idx[cb + e]; sw[e] = d_w[cb + e]; }
  }

  float acc[2][8][4];
  #pragma unroll
  for (int i = 0; i < 2; i++)
    #pragma unroll
    for (int n = 0; n < 8; n++)
      #pragma unroll
      for (int r = 0; r < 4; r++) acc[i][n][r] = 0.0f;

  auto load_chunk = [&](int kc, int s) {
    float* Wh = Whi + s*4352; float* Wl = Wlo + s*4352; float* Xd = Xs + s*4352;
    #pragma unroll
    for (int k = 0; k < 4; k++) {
      int e4 = tid + k*256, kk = e4 >> 5, c = (e4 & 31) << 2;
      cp16(Wh + kk*LDW + c, d_W1hi + (size_t)(kc + kk)*128 + c);
      cp16(Wl + kk*LDW + c, d_W1lo + (size_t)(kc + kk)*128 + c);
      cp16(Xd + kk*LDW + c, xb + (size_t)(kc + kk)*Mq + m0 + c);
    }
  };
  load_chunk(0, 0); cp_commit();
  for (int ch = 0; ch < 4; ch++) {
    if (ch < 3) { load_chunk((ch+1)*32, (ch+1)&1); cp_commit(); cp_wait<1>(); }
    else        { cp_wait<0>(); }
    __syncthreads();
    chunk_mma<8, LDW>(Whi + (ch&1)*4352, Wlo + (ch&1)*4352, Xs + (ch&1)*4352,
                      g, tg, ob, mb, acc);
    __syncthreads();
  }

  // acc -> Zs[o][m]
  #pragma unroll
  for (int i = 0; i < 2; i++)
    #pragma unroll
    for (int n = 0; n < 8; n++) {
      int o = ob + 16*i + g;
      int m = mb + 8*n + 2*tg;
      *(float2*)&Zs[(size_t)o*LDZ + m]     = make_float2(acc[i][n][0], acc[i][n][1]);
      *(float2*)&Zs[(size_t)(o+8)*LDZ + m] = make_float2(acc[i][n][2], acc[i][n][3]);
    }
  __syncthreads();

  // gather-interpolate + store z1 + write back for stats
  int mcol = tid & 127, oh = tid >> 7;
  int i0 = sidx[mcol*3+0], i1 = sidx[mcol*3+1], i2 = sidx[mcol*3+2];
  float w0 = sw[mcol*3+0], w1 = sw[mcol*3+1], w2 = sw[mcol*3+2];
  const float* P0 = d_P + ((size_t)b*Np + i0) * 128;
  const float* P1 = d_P + ((size_t)b*Np + i1) * 128;
  const float* P2 = d_P + ((size_t)b*Np + i2) * 128;
  float* zb = d_z1 + (size_t)b * DoC * Mq + m0 + mcol;
  #pragma unroll 4
  for (int o = oh*64; o < oh*64 + 64; o += 4) {
    float4 q0 = *(const float4*)(P0 + o);
    float4 q1 = *(const float4*)(P1 + o);
    float4 q2 = *(const float4*)(P2 + o);
    float v0 = Zs[(o+0)*LDZ + mcol] + w0*q0.x + w1*q1.x + w2*q2.x;
    float v1 = Zs[(o+1)*LDZ + mcol] + w0*q0.y + w1*q1.y + w2*q2.y;
    float v2 = Zs[(o+2)*LDZ + mcol] + w0*q0.z + w1*q1.z + w2*q2.z;
    float v3 = Zs[(o+3)*LDZ + mcol] + w0*q0.w + w1*q1.w + w2*q2.w;
    zb[(size_t)(o+0)*Mq] = v0;
    zb[(size_t)(o+1)*Mq] = v1;
    zb[(size_t)(o+2)*Mq] = v2;
    zb[(size_t)(o+3)*Mq] = v3;
    Zs[(o+0)*LDZ + mcol] = v0;
    Zs[(o+1)*LDZ + mcol] = v1;
    Zs[(o+2)*LDZ + mcol] = v2;
    Zs[(o+3)*LDZ + mcol] = v3;
  }
  __syncthreads();
  if (tid < 128) {
    const float* zr = &Zs[(size_t)tid * LDZ];
    float s = 0.0f, q = 0.0f;
    #pragma unroll 8
    for (int m = 0; m < 128; m += 4) {
      float4 v = *(const float4*)(zr + m);
      s += v.x + v.y + v.z + v.w;
      q += v.x*v.x + v.y*v.y + v.z*v.z + v.w*v.w;
    }
    d_psum[bx * DoC + tid] = s;
    d_psq [bx * DoC + tid] = q;
  }
}

// ---------------- BN finalize ----------------
__global__ void bn_finalize_kernel(const float* __restrict__ g,
                                   const float* __restrict__ bias, int which) {
  __shared__ float ss[512], sq[512];
  int tid = threadIdx.x;               // 512
  int ch = tid & 127, part = tid >> 7;
  float s = 0.0f, q = 0.0f;
  for (int blk = part; blk < NBLK; blk += 4) {
    s += d_psum[blk * DoC + ch];
    q += d_psq [blk * DoC + ch];
  }
  ss[tid] = s; sq[tid] = q;
  __syncthreads();
  if (tid < 128) {
    float S = ss[tid] + ss[tid+128] + ss[tid+256] + ss[tid+384];
    float Q = sq[tid] + sq[tid+128] + sq[tid+256] + sq[tid+384];
    const float invN = 1.0f / (float)NCOLS;
    float mean = S * invN;
    float var  = Q * invN - mean * mean;
    float rstd = rsqrtf(var + 1e-5f);
    float a = g[tid] * rstd;
    float d = bias[tid] - mean * a;
    float* ab = which ? d_bn2 : d_bn1;
    ab[tid] = a; ab[DoC + tid] = d;
  }
}

// ---------------- z2 = W2 @ relu(bn1(z1)), + block stats (3xTF32 mma) ----------------
__global__ __launch_bounds__(256) void gemm2_kernel() {
  extern __shared__ float smem[];
  float* Whi = smem;
  float* Wlo = smem + 8704;
  float* Xs  = smem + 17408;
  float* Zs  = smem;
  float* sa  = smem + 26112;   // 128
  float* sd  = smem + 26240;   // 128
  int tid = threadIdx.x;
  int lane = tid & 31, warp = tid >> 5;
  int g = lane >> 2, tg = lane & 3;
  int ob = (warp & 3) * 32, mb = (warp >> 2) * 64;
  int bx = blockIdx.x;
  int b = bx >> 7, m0 = (bx & 127) << 7;
  if (tid < 128) { sa[tid] = d_bn1[tid]; sd[tid] = d_bn1[DoC + tid]; }
  const float* zb0 = d_z1 + (size_t)b * DoC * Mq;

  float acc[2][8][4];
  #pragma unroll
  for (int i = 0; i < 2; i++)
    #pragma unroll
    for (int n = 0; n < 8; n++)
      #pragma unroll
      for (int r = 0; r < 4; r++) acc[i][n][r] = 0.0f;

  auto load_chunk = [&](int kc, int s) {
    float* Wh = Whi + s*4352; float* Wl = Wlo + s*4352; float* Xd = Xs + s*4352;
    #pragma unroll
    for (int k = 0; k < 4; k++) {
      int e4 = tid + k*256, kk = e4 >> 5, c = (e4 & 31) << 2;
      cp16(Wh + kk*LDW + c, d_W2hi + (size_t)(kc + kk)*128 + c);
      cp16(Wl + kk*LDW + c, d_W2lo + (size_t)(kc + kk)*128 + c);
      cp16(Xd + kk*LDW + c, zb0 + (size_t)(kc + kk)*Mq + m0 + c);
    }
  };
  load_chunk(0, 0); cp_commit();
  for (int ch = 0; ch < 4; ch++) {
    if (ch < 3) { load_chunk((ch+1)*32, (ch+1)&1); cp_commit(); cp_wait<1>(); }
    else        { cp_wait<0>(); }
    __syncthreads();
    float* Xp = Xs + (ch&1)*4352;
    int kc = ch * 32;
    // relu(bn1(.)) in place on this chunk
    #pragma unroll
    for (int k = 0; k < 4; k++) {
      int e4 = tid + k*256, kk = e4 >> 5, c = (e4 & 31) << 2;
      float A = sa[kc + kk], D = sd[kc + kk];
      float4 v = *(float4*)(Xp + kk*LDW + c);
      v.x = fmaxf(fmaf(A, v.x, D), 0.0f);
      v.y = fmaxf(fmaf(A, v.y, D), 0.0f);
      v.z = fmaxf(fmaf(A, v.z, D), 0.0f);
      v.w = fmaxf(fmaf(A, v.w, D), 0.0f);
      *(float4*)(Xp + kk*LDW + c) = v;
    }
    __syncthreads();
    chunk_mma<8, LDW>(Whi + (ch&1)*4352, Wlo + (ch&1)*4352, Xp, g, tg, ob, mb, acc);
    __syncthreads();
  }

  #pragma unroll
  for (int i = 0; i < 2; i++)
    #pragma unroll
    for (int n = 0; n < 8; n++) {
      int o = ob + 16*i + g;
      int m = mb + 8*n + 2*tg;
      *(float2*)&Zs[(size_t)o*LDZ + m]     = make_float2(acc[i][n][0], acc[i][n][1]);
      *(float2*)&Zs[(size_t)(o+8)*LDZ + m] = make_float2(acc[i][n][2], acc[i][n][3]);
    }
  __syncthreads();

  int mcol = tid & 127, oh = tid >> 7;
  float* zb = d_z2 + (size_t)b * DoC * Mq + m0 + mcol;
  #pragma unroll 4
  for (int o = oh*64; o < oh*64 + 64; o += 4) {
    zb[(size_t)(o+0)*Mq] = Zs[(o+0)*LDZ + mcol];
    zb[(size_t)(o+1)*Mq] = Zs[(o+1)*LDZ + mcol];
    zb[(size_t)(o+2)*Mq] = Zs[(o+2)*LDZ + mcol];
    zb[(size_t)(o+3)*Mq] = Zs[(o+3)*LDZ + mcol];
  }
  if (tid < 128) {
    const float* zr = &Zs[(size_t)tid * LDZ];
    float s = 0.0f, q = 0.0f;
    #pragma unroll 8
    for (int m = 0; m < 128; m += 4) {
      float4 v = *(const float4*)(zr + m);
      s += v.x + v.y + v.z + v.w;
      q += v.x*v.x + v.y*v.y + v.z*v.z + v.w*v.w;
    }
    d_psum[bx * DoC + tid] = s;
    d_psq [bx * DoC + tid] = q;
  }
}

// ---------------- out = relu(bn2(z2)) ----------------
__global__ __launch_bounds__(256) void final_kernel(float* __restrict__ out) {
  int e4 = blockIdx.x * 256 + threadIdx.x;
  int ch = (e4 >> 12) & 127;
  float a = d_bn2[ch], d = d_bn2[DoC + ch];
  float4 v = *((const float4*)d_z2 + e4);
  v.x = fmaxf(fmaf(a, v.x, d), 0.0f);
  v.y = fmaxf(fmaf(a, v.y, d), 0.0f);
  v.z = fmaxf(fmaf(a, v.z, d), 0.0f);
  v.w = fmaxf(fmaf(a, v.w, d), 0.0f);
  *((float4*)out + e4) = v;
}

// ---------------- launch ----------------
extern "C" void kernel_launch(void* const* d_in, const int* in_sizes, int n_in,
                              void* d_out, int out_size) {
  const float* x       = (const float*)d_in[0];
  const float* xyz     = (const float*)d_in[1];
  const float* sub_x   = (const float*)d_in[2];
  const float* sub_xyz = (const float*)d_in[3];
  const float* W1      = (const float*)d_in[4];
  const float* g1      = (const float*)d_in[5];
  const float* b1      = (const float*)d_in[6];
  const float* W2      = (const float*)d_in[7];
  const float* g2      = (const float*)d_in[8];
  const float* b2      = (const float*)d_in[9];
  float* out = (float*)d_out;

  cudaFuncSetAttribute(gemmP_kernel, cudaFuncAttributeMaxDynamicSharedMemorySize, 88064);
  cudaFuncSetAttribute(gemm1_kernel, cudaFuncAttributeMaxDynamicSharedMemorySize, 107520);
  cudaFuncSetAttribute(gemm2_kernel, cudaFuncAttributeMaxDynamicSharedMemorySize, 105472);

  split_w_kernel<<<256, 256>>>(W1, W2);
  knn_kernel<<<128, 256>>>(xyz, sub_xyz);
  knn_merge_kernel<<<128, 256>>>(xyz);
  gemmP_kernel<<<128, 256, 88064>>>(sub_x);
  gemm1_kernel<<<256, 256, 107520>>>(x);
  bn_finalize_kernel<<<1, 512>>>(g1, b1, 0);
  gemm2_kernel<<<256, 256, 105472>>>();
  bn_finalize_kernel<<<1, 512>>>(g2, b2, 1);
  final_kernel<<<4096, 256>>>(out);
}

// round 4
// speedup vs baseline: 1.0384x; 1.0384x over previous
#include <cuda_runtime.h>

#define Bc   2
#define Mq   16384
#define Np   4096
#define Cin  128
#define CsF  256
#define DoC  128
#define NCOLS (Bc*Mq)
#define NBLK  256
#define PH   2048
#define LDW  136      // 128-wide k-major smem rows, pad 8 -> conflict-free frags
#define LDXP 40       // gemmP X tile (32-wide, pad 8)
#define LDZ  136
#define LDZP 40

// ---------------- scratch (device globals) ----------------
__device__ __align__(16) float d_W1t[384*128];   // raw, k-major
__device__ __align__(16) float d_W2t[128*128];
__device__ __align__(16) float d_P  [Bc*Np*DoC];
__device__ float d_cd[Bc*Mq*6];
__device__ int   d_ci[Bc*Mq*6];
__device__ int   d_idx[Bc*Mq*3];
__device__ float d_w  [Bc*Mq*3];
__device__ __align__(16) float d_z1 [Bc*DoC*Mq];
__device__ __align__(16) float d_z2 [Bc*DoC*Mq];
__device__ float d_psum[NBLK*DoC];
__device__ float d_psq [NBLK*DoC];
__device__ float d_bn1[2*DoC];
__device__ float d_bn2[2*DoC];

// ---------------- helpers ----------------
__device__ __forceinline__ void cp16(float* s, const float* g) {
  unsigned sa = (unsigned)__cvta_generic_to_shared(s);
  asm volatile("cp.async.cg.shared.global [%0], [%1], 16;\n" :: "r"(sa), "l"(g));
}
__device__ __forceinline__ void cp_commit() { asm volatile("cp.async.commit_group;\n"); }
template<int N> __device__ __forceinline__ void cp_wait() {
  asm volatile("cp.async.wait_group %0;\n" :: "n"(N));
}
__device__ __forceinline__ void mma8(float* d, const unsigned* a, const unsigned* b) {
  asm("mma.sync.aligned.m16n8k8.row.col.f32.tf32.tf32.f32 "
      "{%0,%1,%2,%3}, {%4,%5,%6,%7}, {%8,%9}, {%0,%1,%2,%3};"
      : "+f"(d[0]), "+f"(d[1]), "+f"(d[2]), "+f"(d[3])
      : "r"(a[0]), "r"(a[1]), "r"(a[2]), "r"(a[3]), "r"(b[0]), "r"(b[1]));
}
__device__ __forceinline__ void split3(float x, unsigned& hi, unsigned& lo) {
  hi = __float_as_uint(x) & 0xffffe000u;
  float r = x - __uint_as_float(hi);
  lo = __float_as_uint(r) & 0xffffe000u;
}

// 3xTF32 over one 16-k chunk. W raw k-major [16][LDW], split on the fly.
// X raw [16][LX]. Warp tile: [ob..ob+32) x [mb..mb+8*NT).
template<int NT, int LX>
__device__ __forceinline__ void chunk_mma16(const float* Wp, const float* Xp,
                                            int g, int tg, int ob, int mb,
                                            float (&acc)[2][NT][4]) {
  #pragma unroll
  for (int s = 0; s < 2; s++) {
    int kr = s * 8;
    unsigned ah[2][4], al[2][4];
    #pragma unroll
    for (int i = 0; i < 2; i++) {
      int o0 = ob + 16*i + g;
      const float* w0 = Wp + (kr+tg)*LDW;
      const float* w1 = Wp + (kr+tg+4)*LDW;
      split3(w0[o0],   ah[i][0], al[i][0]);
      split3(w0[o0+8], ah[i][1], al[i][1]);
      split3(w1[o0],   ah[i][2], al[i][2]);
      split3(w1[o0+8], ah[i][3], al[i][3]);
    }
    #pragma unroll
    for (int n = 0; n < NT; n++) {
      float x0 = Xp[(kr+tg)*LX + mb + 8*n + g];
      float x1 = Xp[(kr+tg+4)*LX + mb + 8*n + g];
      unsigned bh[2], bl[2];
      split3(x0, bh[0], bl[0]);
      split3(x1, bh[1], bl[1]);
      mma8(acc[0][n], al[0], bh);
      mma8(acc[0][n], ah[0], bl);
      mma8(acc[0][n], ah[0], bh);
      mma8(acc[1][n], al[1], bh);
      mma8(acc[1][n], ah[1], bl);
      mma8(acc[1][n], ah[1], bh);
    }
  }
}

// Same, with relu(bn(.)) applied to X elements before split (gemm2).
template<int NT, int LX>
__device__ __forceinline__ void chunk_mma16_bn(const float* Wp, const float* Xp,
                                               const float* sa, const float* sd, int kc,
                                               int g, int tg, int ob, int mb,
                                               float (&acc)[2][NT][4]) {
  #pragma unroll
  for (int s = 0; s < 2; s++) {
    int kr = s * 8;
    float A0 = sa[kc+kr+tg],   D0 = sd[kc+kr+tg];
    float A1 = sa[kc+kr+tg+4], D1 = sd[kc+kr+tg+4];
    unsigned ah[2][4], al[2][4];
    #pragma unroll
    for (int i = 0; i < 2; i++) {
      int o0 = ob + 16*i + g;
      const float* w0 = Wp + (kr+tg)*LDW;
      const float* w1 = Wp + (kr+tg+4)*LDW;
      split3(w0[o0],   ah[i][0], al[i][0]);
      split3(w0[o0+8], ah[i][1], al[i][1]);
      split3(w1[o0],   ah[i][2], al[i][2]);
      split3(w1[o0+8], ah[i][3], al[i][3]);
    }
    #pragma unroll
    for (int n = 0; n < NT; n++) {
      float x0 = fmaxf(fmaf(A0, Xp[(kr+tg)*LX + mb + 8*n + g], D0), 0.0f);
      float x1 = fmaxf(fmaf(A1, Xp[(kr+tg+4)*LX + mb + 8*n + g], D1), 0.0f);
      unsigned bh[2], bl[2];
      split3(x0, bh[0], bl[0]);
      split3(x1, bh[1], bl[1]);
      mma8(acc[0][n], al[0], bh);
      mma8(acc[0][n], ah[0], bl);
      mma8(acc[0][n], ah[0], bh);
      mma8(acc[1][n], al[1], bh);
      mma8(acc[1][n], ah[1], bl);
      mma8(acc[1][n], ah[1], bh);
    }
  }
}

// ---------------- W transpose (raw) ----------------
__global__ __launch_bounds__(256) void transpose_w_kernel(
    const float* __restrict__ W1, const float* __restrict__ W2) {
  int e = blockIdx.x * 256 + threadIdx.x;   // 65536
  if (e < 384*128) {
    int k = e >> 7, o = e & 127;
    d_W1t[e] = W1[o*384 + k];
  } else {
    int e2 = e - 384*128;
    int k = e2 >> 7, o = e2 & 127;
    d_W2t[e2] = W2[o*128 + k];
  }
}

// ---------------- 3-NN search: 2 queries/thread, split point dim in 2 ----------------
__global__ __launch_bounds__(256) void knn_kernel(
    const float* __restrict__ xyz, const float* __restrict__ sub_xyz) {
  __shared__ float4 pts[PH];
  int bx = blockIdx.x;                      // 128 blocks
  int b    = bx >> 6;
  int half = (bx >> 5) & 1;
  int m0   = ((bx & 31) << 9) + threadIdx.x;
  const float* sp = sub_xyz + (size_t)b * 3 * Np + half * PH;
  for (int i = threadIdx.x; i < PH; i += 256) {
    float px = sp[i], py = sp[Np + i], pz = sp[2*Np + i];
    pts[i] = make_float4(px, py, pz, fmaf(px, px, fmaf(py, py, pz*pz)));
  }
  __syncthreads();
  const float* qp = xyz + (size_t)b * 3 * Mq;
  int mA = m0, mB = m0 + 256;
  float nxA = -2.f*qp[mA], nyA = -2.f*qp[Mq+mA], nzA = -2.f*qp[2*Mq+mA];
  float nxB = -2.f*qp[mB], nyB = -2.f*qp[Mq+mB], nzB = -2.f*qp[2*Mq+mB];

  float a0=3.4e38f,a1=3.4e38f,a2=3.4e38f; int ja0=0,ja1=0,ja2=0;
  float b0=3.4e38f,b1=3.4e38f,b2=3.4e38f; int jb0=0,jb1=0,jb2=0;
  #pragma unroll 4
  for (int i = 0; i < PH; i++) {
    float4 p = pts[i];
    float eA = fmaf(nxA, p.x, fmaf(nyA, p.y, fmaf(nzA, p.z, p.w)));
    float eB = fmaf(nxB, p.x, fmaf(nyB, p.y, fmaf(nzB, p.z, p.w)));
    if (eA < a2) {
      if (eA < a1) {
        a2 = a1; ja2 = ja1;
        if (eA < a0) { a1 = a0; ja1 = ja0; a0 = eA; ja0 = i; }
        else         { a1 = eA; ja1 = i; }
      } else { a2 = eA; ja2 = i; }
    }
    if (eB < b2) {
      if (eB < b1) {
        b2 = b1; jb2 = jb1;
        if (eB < b0) { b1 = b0; jb1 = jb0; b0 = eB; jb0 = i; }
        else         { b1 = eB; jb1 = i; }
      } else { b2 = eB; jb2 = i; }
    }
  }
  int off = half * PH;
  size_t baseA = ((size_t)(b * Mq + mA) * 2 + half) * 3;
  d_cd[baseA+0]=a0; d_cd[baseA+1]=a1; d_cd[baseA+2]=a2;
  d_ci[baseA+0]=ja0+off; d_ci[baseA+1]=ja1+off; d_ci[baseA+2]=ja2+off;
  size_t baseB = ((size_t)(b * Mq + mB) * 2 + half) * 3;
  d_cd[baseB+0]=b0; d_cd[baseB+1]=b1; d_cd[baseB+2]=b2;
  d_ci[baseB+0]=jb0+off; d_ci[baseB+1]=jb1+off; d_ci[baseB+2]=jb2+off;
}

// ---------------- merge 6 candidates ----------------
__global__ __launch_bounds__(256) void knn_merge_kernel(const float* __restrict__ xyz) {
  int g = blockIdx.x * 256 + threadIdx.x;
  int b = g >> 14, m = g & (Mq - 1);
  const float* qp = xyz + (size_t)b * 3 * Mq;
  float qx = qp[m], qy = qp[Mq + m], qz = qp[2*Mq + m];
  float qq = fmaf(qx, qx, fmaf(qy, qy, qz*qz));
  float c0 = 3.4e38f, c1 = 3.4e38f, c2 = 3.4e38f;
  int j0 = 0, j1 = 0, j2 = 0;
  size_t base = (size_t)g * 6;
  #pragma unroll
  for (int t = 0; t < 6; t++) {
    float e = d_cd[base + t];
    int  id = d_ci[base + t];
    if (e < c2) {
      if (e < c1) {
        c2 = c1; j2 = j1;
        if (e < c0) { c1 = c0; j1 = j0; c0 = e; j0 = id; }
        else        { c1 = e; j1 = id; }
      } else { c2 = e; j2 = id; }
    }
  }
  float d0  = fmaxf(c0 + qq, 0.0f);
  float d1  = fmaxf(c1 + qq, 0.0f);
  float d2v = fmaxf(c2 + qq, 0.0f);
  float w0 = 1.0f / (d0 + 1e-8f);
  float w1 = 1.0f / (d1 + 1e-8f);
  float w2 = 1.0f / (d2v + 1e-8f);
  float inv = 1.0f / (w0 + w1 + w2);
  d_idx[g*3+0]=j0; d_idx[g*3+1]=j1; d_idx[g*3+2]=j2;
  d_w[g*3+0]=w0*inv; d_w[g*3+1]=w1*inv; d_w[g*3+2]=w2*inv;
}

// ---------------- P = W1[:,128:384] @ sub_x, 128o x 32n tiles, 256 blocks ----------------
__global__ __launch_bounds__(256) void gemmP_kernel(const float* __restrict__ sub_x) {
  extern __shared__ float smem[];
  float* Ws = smem;              // [2][16*136] = 4352
  float* Xs = smem + 4352;       // [2][16*40]  = 1280
  float* Zs = smem;              // epilogue: 128*40 = 5120 (aliases pipeline)
  int tid = threadIdx.x;
  int lane = tid & 31, warp = tid >> 5;
  int g = lane >> 2, tg = lane & 3;
  int ob = (warp & 3) * 32, mb = (warp >> 2) * 16;
  int bx = blockIdx.x;
  int b = bx >> 7, n0 = (bx & 127) << 5;
  const float* xb = sub_x + (size_t)b * CsF * Np;

  float acc[2][2][4];
  #pragma unroll
  for (int i = 0; i < 2; i++)
    #pragma unroll
    for (int n = 0; n < 2; n++)
      #pragma unroll
      for (int r = 0; r < 4; r++) acc[i][n][r] = 0.0f;

  auto load_chunk = [&](int kc, int s) {
    float* Wd = Ws + s*2176; float* Xd = Xs + s*640;
    #pragma unroll
    for (int k = 0; k < 2; k++) {
      int e4 = tid + k*256, kk = e4 >> 5, c = (e4 & 31) << 2;
      cp16(Wd + kk*LDW + c, d_W1t + (size_t)(Cin + kc + kk)*128 + c);
    }
    if (tid < 128) {
      int kk = tid >> 3, c = (tid & 7) << 2;
      cp16(Xd + kk*LDXP + c, xb + (size_t)(kc + kk)*Np + n0 + c);
    }
  };
  load_chunk(0, 0); cp_commit();
  for (int ch = 0; ch < 16; ch++) {
    if (ch < 15) { load_chunk((ch+1)*16, (ch+1)&1); cp_commit(); cp_wait<1>(); }
    else         { cp_wait<0>(); }
    __syncthreads();
    chunk_mma16<2, LDXP>(Ws + (ch&1)*2176, Xs + (ch&1)*640, g, tg, ob, mb, acc);
    __syncthreads();
  }

  // stage Z[o][n] then store P[n][o]
  #pragma unroll
  for (int i = 0; i < 2; i++)
    #pragma unroll
    for (int n = 0; n < 2; n++) {
      int o = ob + 16*i + g;
      int m = mb + 8*n + 2*tg;
      *(float2*)&Zs[(size_t)o*LDZP + m]     = make_float2(acc[i][n][0], acc[i][n][1]);
      *(float2*)&Zs[(size_t)(o+8)*LDZP + m] = make_float2(acc[i][n][2], acc[i][n][3]);
    }
  __syncthreads();
  int nl = tid & 31, oh = tid >> 5;   // 8 o-chunks of 16
  float* dst = d_P + ((size_t)b * Np + n0 + nl) * 128;
  #pragma unroll
  for (int o = oh*16; o < oh*16 + 16; o += 4) {
    float4 v = make_float4(Zs[(o+0)*LDZP + nl], Zs[(o+1)*LDZP + nl],
                           Zs[(o+2)*LDZP + nl], Zs[(o+3)*LDZP + nl]);
    *(float4*)(dst + o) = v;
  }
}

// ---------------- z1 = W1a @ x + gather(P), + block stats ----------------
__global__ __launch_bounds__(256, 2) void gemm1_kernel(const float* __restrict__ x) {
  extern __shared__ float smem[];
  float* Ws   = smem;                  // [2][16*136] = 4352
  float* Xs   = smem + 4352;           // [2][16*136] = 4352
  float* Zs   = smem;                  // epilogue half: 64*136 = 8704 (aliases)
  int*   sidx = (int*)(smem + 8704);   // 384
  float* sw   = smem + 9088;           // 384
  int tid = threadIdx.x;
  int lane = tid & 31, warp = tid >> 5;
  int g = lane >> 2, tg = lane & 3;
  int ob = (warp & 3) * 32, mb = (warp >> 2) * 64;
  int bx = blockIdx.x;
  int b = bx >> 7, m0 = (bx & 127) << 7;
  const float* xb = x + (size_t)b * Cin * Mq;

  {
    size_t cb = ((size_t)(b * Mq + m0)) * 3;
    for (int e = tid; e < 384; e += 256) { sidx[e] = d_idx[cb + e]; sw[e] = d_w[cb + e]; }
  }

  float acc[2][8][4];
  #pragma unroll
  for (int i = 0; i < 2; i++)
    #pragma unroll
    for (int n = 0; n < 8; n++)
      #pragma unroll
      for (int r = 0; r < 4; r++) acc[i][n][r] = 0.0f;

  auto load_chunk = [&](int kc, int s) {
    float* Wd = Ws + s*2176; float* Xd = Xs + s*2176;
    #pragma unroll
    for (int k = 0; k < 2; k++) {
      int e4 = tid + k*256, kk = e4 >> 5, c = (e4 & 31) << 2;
      cp16(Wd + kk*LDW + c, d_W1t + (size_t)(kc + kk)*128 + c);
      cp16(Xd + kk*LDW + c, xb + (size_t)(kc + kk)*Mq + m0 + c);
    }
  };
  load_chunk(0, 0); cp_commit();
  for (int ch = 0; ch < 8; ch++) {
    if (ch < 7) { load_chunk((ch+1)*16, (ch+1)&1); cp_commit(); cp_wait<1>(); }
    else        { cp_wait<0>(); }
    __syncthreads();
    chunk_mma16<8, LDW>(Ws + (ch&1)*2176, Xs + (ch&1)*2176, g, tg, ob, mb, acc);
    __syncthreads();
  }

  // epilogue: two channel-halves staged through Zs
  int mcol = tid & 127, oq = tid >> 7;
  int i0 = sidx[mcol*3+0], i1 = sidx[mcol*3+1], i2 = sidx[mcol*3+2];
  float w0 = sw[mcol*3+0], w1 = sw[mcol*3+1], w2 = sw[mcol*3+2];
  float* zb = d_z1 + (size_t)b * DoC * Mq + m0 + mcol;
  #pragma unroll
  for (int h = 0; h < 2; h++) {
    __syncthreads();
    if (((warp & 3) >> 1) == h) {
      int obl = (warp & 1) * 32;
      #pragma unroll
      for (int i = 0; i < 2; i++)
        #pragma unroll
        for (int n = 0; n < 8; n++) {
          int o = obl + 16*i + g;
          int m = mb + 8*n + 2*tg;
          *(float2*)&Zs[(size_t)o*LDZ + m]     = make_float2(acc[i][n][0], acc[i][n][1]);
          *(float2*)&Zs[(size_t)(o+8)*LDZ + m] = make_float2(acc[i][n][2], acc[i][n][3]);
        }
    }
    __syncthreads();
    const float* P0 = d_P + ((size_t)b*Np + i0) * 128 + h*64;
    const float* P1 = d_P + ((size_t)b*Np + i1) * 128 + h*64;
    const float* P2 = d_P + ((size_t)b*Np + i2) * 128 + h*64;
    #pragma unroll 2
    for (int o = oq*32; o < oq*32 + 32; o += 4) {
      float4 q0 = *(const float4*)(P0 + o);
      float4 q1 = *(const float4*)(P1 + o);
      float4 q2 = *(const float4*)(P2 + o);
      float v0 = Zs[(o+0)*LDZ + mcol] + w0*q0.x + w1*q1.x + w2*q2.x;
      float v1 = Zs[(o+1)*LDZ + mcol] + w0*q0.y + w1*q1.y + w2*q2.y;
      float v2 = Zs[(o+2)*LDZ + mcol] + w0*q0.z + w1*q1.z + w2*q2.z;
      float v3 = Zs[(o+3)*LDZ + mcol] + w0*q0.w + w1*q1.w + w2*q2.w;
      zb[(size_t)(h*64+o+0)*Mq] = v0;
      zb[(size_t)(h*64+o+1)*Mq] = v1;
      zb[(size_t)(h*64+o+2)*Mq] = v2;
      zb[(size_t)(h*64+o+3)*Mq] = v3;
      Zs[(o+0)*LDZ + mcol] = v0;
      Zs[(o+1)*LDZ + mcol] = v1;
      Zs[(o+2)*LDZ + mcol] = v2;
      Zs[(o+3)*LDZ + mcol] = v3;
    }
    __syncthreads();
    if (tid < 64) {
      const float* zr = &Zs[(size_t)tid * LDZ];
      float s = 0.0f, q = 0.0f;
      #pragma unroll 8
      for (int m = 0; m < 128; m += 4) {
        float4 v = *(const float4*)(zr + m);
        s += v.x + v.y + v.z + v.w;
        q += v.x*v.x + v.y*v.y + v.z*v.z + v.w*v.w;
      }
      d_psum[bx * DoC + h*64 + tid] = s;
      d_psq [bx * DoC + h*64 + tid] = q;
    }
  }
}

// ---------------- BN finalize ----------------
__global__ void bn_finalize_kernel(const float* __restrict__ g,
                                   const float* __restrict__ bias, int which) {
  __shared__ float ss[512], sq[512];
  int tid = threadIdx.x;
  int ch = tid & 127, part = tid >> 7;
  float s = 0.0f, q = 0.0f;
  for (int blk = part; blk < NBLK; blk += 4) {
    s += d_psum[blk * DoC + ch];
    q += d_psq [blk * DoC + ch];
  }
  ss[tid] = s; sq[tid] = q;
  __syncthreads();
  if (tid < 128) {
    float S = ss[tid] + ss[tid+128] + ss[tid+256] + ss[tid+384];
    float Q = sq[tid] + sq[tid+128] + sq[tid+256] + sq[tid+384];
    const float invN = 1.0f / (float)NCOLS;
    float mean = S * invN;
    float var  = Q * invN - mean * mean;
    float rstd = rsqrtf(var + 1e-5f);
    float a = g[tid] * rstd;
    float d = bias[tid] - mean * a;
    float* ab = which ? d_bn2 : d_bn1;
    ab[tid] = a; ab[DoC + tid] = d;
  }
}

// ---------------- z2 = W2 @ relu(bn1(z1)), + block stats ----------------
__global__ __launch_bounds__(256, 2) void gemm2_kernel() {
  extern __shared__ float smem[];
  float* Ws = smem;               // [2][2176]
  float* Xs = smem + 4352;        // [2][2176]
  float* Zs = smem;               // epilogue half 64*136 = 8704
  float* sa = smem + 8704;        // 128
  float* sd = smem + 8832;        // 128
  int tid = threadIdx.x;
  int lane = tid & 31, warp = tid >> 5;
  int g = lane >> 2, tg = lane & 3;
  int ob = (warp & 3) * 32, mb = (warp >> 2) * 64;
  int bx = blockIdx.x;
  int b = bx >> 7, m0 = (bx & 127) << 7;
  if (tid < 128) { sa[tid] = d_bn1[tid]; sd[tid] = d_bn1[DoC + tid]; }
  const float* zb0 = d_z1 + (size_t)b * DoC * Mq;

  float acc[2][8][4];
  #pragma unroll
  for (int i = 0; i < 2; i++)
    #pragma unroll
    for (int n = 0; n < 8; n++)
      #pragma unroll
      for (int r = 0; r < 4; r++) acc[i][n][r] = 0.0f;

  auto load_chunk = [&](int kc, int s) {
    float* Wd = Ws + s*2176; float* Xd = Xs + s*2176;
    #pragma unroll
    for (int k = 0; k < 2; k++) {
      int e4 = tid + k*256, kk = e4 >> 5, c = (e4 & 31) << 2;
      cp16(Wd + kk*LDW + c, d_W2t + (size_t)(kc + kk)*128 + c);
      cp16(Xd + kk*LDW + c, zb0 + (size_t)(kc + kk)*Mq + m0 + c);
    }
  };
  load_chunk(0, 0); cp_commit();
  for (int ch = 0; ch < 8; ch++) {
    if (ch < 7) { load_chunk((ch+1)*16, (ch+1)&1); cp_commit(); cp_wait<1>(); }
    else        { cp_wait<0>(); }
    __syncthreads();
    chunk_mma16_bn<8, LDW>(Ws + (ch&1)*2176, Xs + (ch&1)*2176, sa, sd, ch*16,
                           g, tg, ob, mb, acc);
    __syncthreads();
  }

  float* zb = d_z2 + (size_t)b * DoC * Mq + m0 + (tid & 127);
  int mcol = tid & 127, oq = tid >> 7;
  #pragma unroll
  for (int h = 0; h < 2; h++) {
    __syncthreads();
    if (((warp & 3) >> 1) == h) {
      int obl = (warp & 1) * 32;
      #pragma unroll
      for (int i = 0; i < 2; i++)
        #pragma unroll
        for (int n = 0; n < 8; n++) {
          int o = obl + 16*i + g;
          int m = mb + 8*n + 2*tg;
          *(float2*)&Zs[(size_t)o*LDZ + m]     = make_float2(acc[i][n][0], acc[i][n][1]);
          *(float2*)&Zs[(size_t)(o+8)*LDZ + m] = make_float2(acc[i][n][2], acc[i][n][3]);
        }
    }
    __syncthreads();
    #pragma unroll 2
    for (int o = oq*32; o < oq*32 + 32; o += 4) {
      zb[(size_t)(h*64+o+0)*Mq] = Zs[(o+0)*LDZ + mcol];
      zb[(size_t)(h*64+o+1)*Mq] = Zs[(o+1)*LDZ + mcol];
      zb[(size_t)(h*64+o+2)*Mq] = Zs[(o+2)*LDZ + mcol];
      zb[(size_t)(h*64+o+3)*Mq] = Zs[(o+3)*LDZ + mcol];
    }
    __syncthreads();
    if (tid < 64) {
      const float* zr = &Zs[(size_t)tid * LDZ];
      float s = 0.0f, q = 0.0f;
      #pragma unroll 8
      for (int m = 0; m < 128; m += 4) {
        float4 v = *(const float4*)(zr + m);
        s += v.x + v.y + v.z + v.w;
        q += v.x*v.x + v.y*v.y + v.z*v.z + v.w*v.w;
      }
      d_psum[bx * DoC + h*64 + tid] = s;
      d_psq [bx * DoC + h*64 + tid] = q;
    }
  }
}

// ---------------- out = relu(bn2(z2)) ----------------
__global__ __launch_bounds__(256) void final_kernel(float* __restrict__ out) {
  int e4 = blockIdx.x * 256 + threadIdx.x;
  int ch = (e4 >> 12) & 127;
  float a = d_bn2[ch], d = d_bn2[DoC + ch];
  float4 v = *((const float4*)d_z2 + e4);
  v.x = fmaxf(fmaf(a, v.x, d), 0.0f);
  v.y = fmaxf(fmaf(a, v.y, d), 0.0f);
  v.z = fmaxf(fmaf(a, v.z, d), 0.0f);
  v.w = fmaxf(fmaf(a, v.w, d), 0.0f);
  *((float4*)out + e4) = v;
}

// ---------------- launch ----------------
extern "C" void kernel_launch(void* const* d_in, const int* in_sizes, int n_in,
                              void* d_out, int out_size) {
  const float* x       = (const float*)d_in[0];
  const float* xyz     = (const float*)d_in[1];
  const float* sub_x   = (const float*)d_in[2];
  const float* sub_xyz = (const float*)d_in[3];
  const float* W1      = (const float*)d_in[4];
  const float* g1      = (const float*)d_in[5];
  const float* b1      = (const float*)d_in[6];
  const float* W2      = (const float*)d_in[7];
  const float* g2      = (const float*)d_in[8];
  const float* b2      = (const float*)d_in[9];
  float* out = (float*)d_out;

  transpose_w_kernel<<<256, 256>>>(W1, W2);
  knn_kernel<<<128, 256>>>(xyz, sub_xyz);
  knn_merge_kernel<<<128, 256>>>(xyz);
  gemmP_kernel<<<256, 256, 5632*4>>>(sub_x);
  gemm1_kernel<<<256, 256, 9472*4>>>(x);
  bn_finalize_kernel<<<1, 512>>>(g1, b1, 0);
  gemm2_kernel<<<256, 256, 8960*4>>>();
  bn_finalize_kernel<<<1, 512>>>(g2, b2, 1);
  final_kernel<<<4096, 256>>>(out);
}